// round 1
// baseline (speedup 1.0000x reference)
#include <cuda_runtime.h>
#include <cstdint>

// MultiStepIFNode: multi-step integrate-and-fire over T=16 timesteps.
// x_seq: (16, 32, 128, 32, 32) fp32. spike_seq: same shape.
// Per neuron i: v=0; for t: v += x[t,i]; s = (v>=1); out[t,i]=s; v -= s;
//
// Pure HBM streaming problem: 256 MiB in + 256 MiB out.
// One thread owns 4 consecutive neurons (float4), keeps v in registers
// across the whole T loop. Loads per timestep are coalesced; the 16 loads
// are address-independent so the unrolled loop exposes full MLP.

static constexpr int T_STEPS = 16;

__global__ __launch_bounds__(256) void if_multistep_kernel(
    const float4* __restrict__ x,   // T * n4 float4s
    float4* __restrict__ out,       // T * n4 float4s
    int n4)                         // float4s per timestep (N/4)
{
    int i = blockIdx.x * blockDim.x + threadIdx.x;
    if (i >= n4) return;

    float vx = 0.f, vy = 0.f, vz = 0.f, vw = 0.f;

    #pragma unroll
    for (int t = 0; t < T_STEPS; t++) {
        float4 xt = __ldg(&x[(size_t)t * n4 + i]);
        vx += xt.x;
        vy += xt.y;
        vz += xt.z;
        vw += xt.w;

        float4 s;
        s.x = (vx >= 1.0f) ? 1.0f : 0.0f;
        s.y = (vy >= 1.0f) ? 1.0f : 0.0f;
        s.z = (vz >= 1.0f) ? 1.0f : 0.0f;
        s.w = (vw >= 1.0f) ? 1.0f : 0.0f;

        vx -= s.x;
        vy -= s.y;
        vz -= s.z;
        vw -= s.w;

        out[(size_t)t * n4 + i] = s;
    }
}

extern "C" void kernel_launch(void* const* d_in, const int* in_sizes, int n_in,
                              void* d_out, int out_size)
{
    const float4* x = (const float4*)d_in[0];
    float4* out = (float4*)d_out;

    // out_size = T * N elements; N divisible by 4.
    int n_per_step = out_size / T_STEPS;   // 4,194,304
    int n4 = n_per_step / 4;               // 1,048,576

    const int threads = 256;
    int blocks = (n4 + threads - 1) / threads;
    if_multistep_kernel<<<blocks, threads>>>(x, out, n4);
}

// round 2
// speedup vs baseline: 1.0166x; 1.0166x over previous
#include <cuda_runtime.h>
#include <cstdint>

// MultiStepIFNode: T=16 integrate-and-fire, pure HBM streaming (256 MiB in,
// 256 MiB out). R2 changes vs R1:
//  - Batch 8 timestep loads into registers BEFORE consuming them: raises
//    per-thread MLP from ~2 (reg-capped at 32) to 8. __launch_bounds__(256,3)
//    gives ptxas ~80 regs to hold the batch.
//  - __ldcs / __stcs streaming hints: this data is touched exactly once;
//    evict-first keeps L2 from thrashing between read lines and
//    write-allocated store lines.

static constexpr int T_STEPS = 16;
static constexpr int T_HALF  = 8;

__global__ __launch_bounds__(256, 3) void if_multistep_kernel(
    const float4* __restrict__ x,   // T * n4 float4s
    float4* __restrict__ out,       // T * n4 float4s
    int n4)                         // float4s per timestep (N/4)
{
    int i = blockIdx.x * blockDim.x + threadIdx.x;
    if (i >= n4) return;

    float vx = 0.f, vy = 0.f, vz = 0.f, vw = 0.f;

    #pragma unroll
    for (int half = 0; half < 2; half++) {
        // Front-batch 8 independent loads -> 8 outstanding DRAM requests
        float4 xt[T_HALF];
        #pragma unroll
        for (int t = 0; t < T_HALF; t++) {
            xt[t] = __ldcs(&x[(size_t)(half * T_HALF + t) * n4 + i]);
        }

        // Consume: the v-chain is 4-cycle FADD latency, trivially hidden
        #pragma unroll
        for (int t = 0; t < T_HALF; t++) {
            vx += xt[t].x;
            vy += xt[t].y;
            vz += xt[t].z;
            vw += xt[t].w;

            float4 s;
            s.x = (vx >= 1.0f) ? 1.0f : 0.0f;
            s.y = (vy >= 1.0f) ? 1.0f : 0.0f;
            s.z = (vz >= 1.0f) ? 1.0f : 0.0f;
            s.w = (vw >= 1.0f) ? 1.0f : 0.0f;

            vx -= s.x;
            vy -= s.y;
            vz -= s.z;
            vw -= s.w;

            __stcs(&out[(size_t)(half * T_HALF + t) * n4 + i], s);
        }
    }
}

extern "C" void kernel_launch(void* const* d_in, const int* in_sizes, int n_in,
                              void* d_out, int out_size)
{
    const float4* x = (const float4*)d_in[0];
    float4* out = (float4*)d_out;

    int n_per_step = out_size / T_STEPS;   // 4,194,304
    int n4 = n_per_step / 4;               // 1,048,576

    const int threads = 256;
    int blocks = (n4 + threads - 1) / threads;
    if_multistep_kernel<<<blocks, threads>>>(x, out, n4);
}